// round 1
// baseline (speedup 1.0000x reference)
#include <cuda_runtime.h>
#include <math.h>

#define G    15
#define G3   3375
#define NB   4
#define NPTS 300000
#define PPC  (NB*NPTS)          // 1,200,000 points per cloud

// ---------------- scratch (device globals; no allocations allowed) ----------
__device__ float g_grid[NB*12*G3];     // [B,12,15,15,15] scatter-max scenes
__device__ float g_bufA[NB*8*512];     // conv output (pre-BN)  [B,8,8,8,8]
__device__ float g_bufB[NB*8*512];     // BN output / conv input

// ---------------------------------------------------------------------------
__global__ void zero_grid_kernel() {
    int i = blockIdx.x*blockDim.x + threadIdx.x;
    if (i < NB*12*G3) g_grid[i] = 0.f;
}

// ---------------- point stage: disty -> MLP -> scatter-max ------------------
// 4 points per thread; weights staged in shared and reused across the 4 points.
__global__ void point_kernel(const float* __restrict__ pts,
                             const float* __restrict__ W1, const float* __restrict__ B1,
                             const float* __restrict__ W2, const float* __restrict__ B2,
                             const float* __restrict__ W3, const float* __restrict__ B3,
                             int chan_off)
{
    __shared__ float sW1[192], sB1[16], sW2[256], sB2[16], sW3[64], sB3[4];
    int t = threadIdx.x;
    for (int i=t;i<192;i+=blockDim.x) sW1[i]=W1[i];
    for (int i=t;i<256;i+=blockDim.x) sW2[i]=W2[i];
    for (int i=t;i<64; i+=blockDim.x) sW3[i]=W3[i];
    if (t<16){ sB1[t]=B1[t]; sB2[t]=B2[t]; }
    if (t<4)  sB3[t]=B3[t];
    __syncthreads();

    long tid = (long)blockIdx.x*blockDim.x + t;
    long p0  = tid*4;
    if (p0 >= PPC) return;

    // 4 consecutive points = 12 floats, 48B aligned -> 3x float4
    const float4* v = (const float4*)(pts + p0*3);
    float4 va=v[0], vb=v[1], vc=v[2];
    float px[4]={va.x,va.w,vb.z,vc.y};
    float py[4]={va.y,vb.x,vb.w,vc.z};
    float pz[4]={va.z,vb.y,vc.x,vc.w};

    const float CLIPHI = 15.0f - 1e-4f;
    float X[4][12];
    int   cellidx[4];
    int   bidx = (int)(p0 / NPTS);   // 300000 % 4 == 0 -> all 4 points same batch

    #pragma unroll
    for (int i=0;i<4;i++){
        float cx = floorf(fminf(fmaxf(px[i],0.f), CLIPHI));
        float cy = floorf(fminf(fmaxf(py[i],0.f), CLIPHI));
        float cz = floorf(fminf(fmaxf(pz[i],0.f), CLIPHI));
        float ocx = px[i]-(cx+0.5f), ocy = py[i]-(cy+0.5f), ocz = pz[i]-(cz+0.5f);
        float olx = px[i]-cx,        oly = py[i]-cy,        olz = pz[i]-cz;
        float oux = px[i]-(cx+1.f),  ouy = py[i]-(cy+1.f),  ouz = pz[i]-(cz+1.f);
        X[i][0]=ocx; X[i][1]=ocy; X[i][2]=ocz;
        X[i][3]=olx; X[i][4]=oly; X[i][5]=olz;
        X[i][6]=oux; X[i][7]=ouy; X[i][8]=ouz;
        X[i][9]  = sqrtf(ocx*ocx+ocy*ocy+ocz*ocz);
        X[i][10] = sqrtf(olx*olx+oly*oly+olz*olz);
        X[i][11] = sqrtf(oux*oux+ouy*ouy+ouz*ouz);
        cellidx[i] = ((int)cx*G + (int)cy)*G + (int)cz;
    }

    // layer 1: 12 -> 16, ELU
    float H[4][16];
    #pragma unroll
    for (int j=0;j<16;j++){
        float a0=sB1[j], a1=sB1[j], a2=sB1[j], a3=sB1[j];
        #pragma unroll
        for (int k=0;k<12;k++){
            float w = sW1[k*16+j];
            a0 += X[0][k]*w; a1 += X[1][k]*w; a2 += X[2][k]*w; a3 += X[3][k]*w;
        }
        H[0][j] = a0>0.f ? a0 : (__expf(a0)-1.f);
        H[1][j] = a1>0.f ? a1 : (__expf(a1)-1.f);
        H[2][j] = a2>0.f ? a2 : (__expf(a2)-1.f);
        H[3][j] = a3>0.f ? a3 : (__expf(a3)-1.f);
    }

    // layer 2: 16 -> 16, ELU
    float H2[4][16];
    #pragma unroll
    for (int j=0;j<16;j++){
        float a0=sB2[j], a1=sB2[j], a2=sB2[j], a3=sB2[j];
        #pragma unroll
        for (int k=0;k<16;k++){
            float w = sW2[k*16+j];
            a0 += H[0][k]*w; a1 += H[1][k]*w; a2 += H[2][k]*w; a3 += H[3][k]*w;
        }
        H2[0][j] = a0>0.f ? a0 : (__expf(a0)-1.f);
        H2[1][j] = a1>0.f ? a1 : (__expf(a1)-1.f);
        H2[2][j] = a2>0.f ? a2 : (__expf(a2)-1.f);
        H2[3][j] = a3>0.f ? a3 : (__expf(a3)-1.f);
    }

    // layer 3: 16 -> 4 (no activation) + scatter-max (floor is 0)
    #pragma unroll
    for (int i=0;i<4;i++){
        int base = (bidx*12 + chan_off)*G3 + cellidx[i];
        #pragma unroll
        for (int j=0;j<4;j++){
            float a = sB3[j];
            #pragma unroll
            for (int k=0;k<16;k++) a += H2[i][k]*sW3[k*4+j];
            if (a > 0.f)   // grid floor is 0; positive floats order as ints
                atomicMax((int*)&g_grid[base + j*G3], __float_as_int(a));
        }
    }
}

// ---------------- conv1: 12->8, k5, stride2, pad2, in 15^3 -> out 8^3 -------
// grid (oc=8, od=8, b=4), 64 threads = (oh,ow). Two ic-halves to fit smem.
// Bias omitted: per-channel bias cancels exactly under BatchNorm mean-subtract.
__global__ void conv1_kernel(const float* __restrict__ w)
{
    int oc=blockIdx.x, od=blockIdx.y, b=blockIdx.z;
    int t=threadIdx.x, oh=t>>3, ow=t&7;
    __shared__ float sIn[6][5][15][15];   // 27 KB
    __shared__ float sW[750];             // 3 KB

    float acc = 0.f;
    for (int half=0; half<2; half++){
        int ic0 = half*6;
        __syncthreads();
        for (int i=t; i<6*5*225; i+=64){
            int ic  = i/(5*225);
            int rem = i%(5*225);
            int kd  = rem/225;
            int hw  = rem%225;
            int id  = od*2 - 2 + kd;
            float val = 0.f;
            if ((unsigned)id < 15u)
                val = g_grid[(b*12 + ic0 + ic)*G3 + id*225 + hw];
            ((float*)sIn)[i] = val;
        }
        for (int i=t; i<750; i+=64) sW[i] = w[(oc*12 + ic0)*125 + i];
        __syncthreads();

        #pragma unroll
        for (int ic=0; ic<6; ic++)
        #pragma unroll
        for (int kd=0; kd<5; kd++)
        #pragma unroll
        for (int kh=0; kh<5; kh++){
            int ih = oh*2 - 2 + kh;
            if ((unsigned)ih < 15u){
                #pragma unroll
                for (int kw=0; kw<5; kw++){
                    int iw = ow*2 - 2 + kw;
                    if ((unsigned)iw < 15u)
                        acc += sIn[ic][kd][ih][iw] * sW[ic*125 + kd*25 + kh*5 + kw];
                }
            }
        }
    }
    g_bufA[((b*8+oc)*8 + od)*64 + t] = acc;
}

// ---------------- convs 2..7: 8->8, k5, stride1, pad2, 8^3 -> 8^3 -----------
__global__ void convs_kernel(const float* __restrict__ w)
{
    int oc=blockIdx.x, od=blockIdx.y, b=blockIdx.z;
    int t=threadIdx.x, oh=t>>3, ow=t&7;
    __shared__ float sIn[8][5][12][12];   // padded (+2 each side), 23 KB
    __shared__ float sW[1000];

    for (int i=t; i<8*5*144; i+=64){
        int ic  = i/720;
        int rem = i%720;
        int kd  = rem/144;
        int ph  = (rem%144)/12;
        int pw  = rem%12;
        int id  = od - 2 + kd, ih = ph - 2, iw = pw - 2;
        float val = 0.f;
        if ((unsigned)id < 8u && (unsigned)ih < 8u && (unsigned)iw < 8u)
            val = g_bufB[((b*8+ic)*8 + id)*64 + ih*8 + iw];
        ((float*)sIn)[i] = val;
    }
    for (int i=t; i<1000; i+=64) sW[i] = w[oc*1000 + i];
    __syncthreads();

    float acc = 0.f;
    #pragma unroll
    for (int ic=0; ic<8; ic++)
    #pragma unroll
    for (int kd=0; kd<5; kd++)
    #pragma unroll
    for (int kh=0; kh<5; kh++)
    #pragma unroll
    for (int kw=0; kw<5; kw++)
        acc += sIn[ic][kd][oh+kh][ow+kw] * sW[ic*125 + kd*25 + kh*5 + kw];

    g_bufA[((b*8+oc)*8 + od)*64 + t] = acc;
}

// ---------------- fused BN (batch stats) + ELU ------------------------------
// One block per channel owns all 2048 values -> deterministic two-pass stats.
// Reads g_bufA; writes dst (or g_bufB when dst == nullptr).
__global__ void bn_kernel(float* dst, const float* __restrict__ gamma,
                          const float* __restrict__ beta)
{
    int c = blockIdx.x, t = threadIdx.x;           // 8 blocks x 256 threads
    __shared__ float red[256];
    float* out = dst ? dst : g_bufB;

    float yv[8]; int idx[8];
    float s = 0.f;
    #pragma unroll
    for (int r=0;r<8;r++){
        int e  = t + r*256;                        // 0..2047 = (b, spatial)
        int bb = e >> 9, sp = e & 511;
        idx[r] = (bb*8 + c)*512 + sp;
        yv[r]  = g_bufA[idx[r]];
        s += yv[r];
    }
    red[t] = s; __syncthreads();
    for (int o=128;o>0;o>>=1){ if (t<o) red[t]+=red[t+o]; __syncthreads(); }
    float m = red[0] * (1.f/2048.f);
    __syncthreads();

    float s2 = 0.f;
    #pragma unroll
    for (int r=0;r<8;r++){ float d = yv[r]-m; s2 += d*d; }
    red[t] = s2; __syncthreads();
    for (int o=128;o>0;o>>=1){ if (t<o) red[t]+=red[t+o]; __syncthreads(); }
    float var = red[0] * (1.f/2048.f);

    float sc = rsqrtf(var + 1e-5f) * gamma[c];
    float bt = beta[c];
    #pragma unroll
    for (int r=0;r<8;r++){
        float v = (yv[r]-m)*sc + bt;
        out[idx[r]] = v>0.f ? v : (__expf(v)-1.f);
    }
}

// ---------------------------------------------------------------------------
extern "C" void kernel_launch(void* const* d_in, const int* in_sizes, int n_in,
                              void* d_out, int out_size)
{
    const float* goals       = (const float*)d_in[0];
    const float* inputs      = (const float*)d_in[1];
    const float* backgrounds = (const float*)d_in[2];
    const float* W1 = (const float*)d_in[3];
    const float* b1 = (const float*)d_in[4];
    const float* W2 = (const float*)d_in[5];
    const float* b2 = (const float*)d_in[6];
    const float* W3 = (const float*)d_in[7];
    const float* b3 = (const float*)d_in[8];
    const float* conv1_w = (const float*)d_in[9];
    // d_in[10] = conv1_b : cancels under BN, unused
    const float* bn1_g   = (const float*)d_in[11];
    const float* bn1_b   = (const float*)d_in[12];
    const float* convs_w = (const float*)d_in[13];
    // d_in[14] = convs_b : cancels under BN, unused
    const float* bns_g   = (const float*)d_in[15];
    const float* bns_b   = (const float*)d_in[16];
    float* out = (float*)d_out;

    zero_grid_kernel<<<(NB*12*G3 + 255)/256, 256>>>();

    int pblocks = (PPC/4 + 255)/256;
    // scenes channel order: [inputs, goals, backgrounds]
    point_kernel<<<pblocks,256>>>(inputs,      W1,b1,W2,b2,W3,b3, 0);
    point_kernel<<<pblocks,256>>>(goals,       W1,b1,W2,b2,W3,b3, 4);
    point_kernel<<<pblocks,256>>>(backgrounds, W1,b1,W2,b2,W3,b3, 8);

    dim3 cg(8,8,4);
    conv1_kernel<<<cg,64>>>(conv1_w);
    bn_kernel<<<8,256>>>(nullptr, bn1_g, bn1_b);

    for (int i=0;i<6;i++){
        convs_kernel<<<cg,64>>>(convs_w + i*8000);
        bn_kernel<<<8,256>>>(i==5 ? out : nullptr, bns_g + i*8, bns_b + i*8);
    }
}

// round 3
// speedup vs baseline: 1.6050x; 1.6050x over previous
#include <cuda_runtime.h>
#include <math.h>

#define G     15
#define NB    4
#define NPTS  300000
#define PPC   (NB*NPTS)

// padded grid: [B][12][19][19][21-row] ; per-channel stride 7584 (16B aligned)
#define PD    19
#define ROWS  21
#define CSTR  7584                 // >= 19*19*21 = 7581, /4 ok
#define BSTR  (12*CSTR)
#define GRIDN (NB*BSTR)            // 364032

typedef unsigned long long ull;

__device__ float  g_grid[GRIDN];
__device__ float  g_bufA[NB*8*512];
__device__ float  g_bufB[NB*8*512];
__device__ float2 g_slots0[32];
__device__ float2 g_slots1[32];

// ---------------- packed f32x2 helpers --------------------------------------
__device__ __forceinline__ ull pack2(float lo, float hi){
    ull r; asm("mov.b64 %0, {%1,%2};" : "=l"(r) : "f"(lo), "f"(hi)); return r;
}
__device__ __forceinline__ void unpack2(ull v, float& lo, float& hi){
    asm("mov.b64 {%0,%1}, %2;" : "=f"(lo), "=f"(hi) : "l"(v));
}
__device__ __forceinline__ ull fma2(ull a, ull b, ull c){
    ull d; asm("fma.rn.f32x2 %0, %1, %2, %3;" : "=l"(d) : "l"(a), "l"(b), "l"(c)); return d;
}
__device__ __forceinline__ float eluf(float x){ return x > 0.f ? x : (__expf(x)-1.f); }
__device__ __forceinline__ ull elu2(ull v){
    float lo, hi; unpack2(v, lo, hi);
    return pack2(eluf(lo), eluf(hi));
}

// ---------------------------------------------------------------------------
__global__ void zero_grid_kernel(){
    int i = blockIdx.x*blockDim.x + threadIdx.x;
    if (i < GRIDN) g_grid[i] = 0.f;
}

// ---------------- point stage: disty -> MLP (f32x2) -> scatter-max ----------
__device__ __forceinline__ void disty_one(float px, float py, float pz,
                                          float f[12], int& cellpad)
{
    const float CLIPHI = 15.0f - 1e-4f;
    float cx = floorf(fminf(fmaxf(px,0.f), CLIPHI));
    float cy = floorf(fminf(fmaxf(py,0.f), CLIPHI));
    float cz = floorf(fminf(fmaxf(pz,0.f), CLIPHI));
    float ocx = px-(cx+0.5f), ocy = py-(cy+0.5f), ocz = pz-(cz+0.5f);
    float olx = px-cx,        oly = py-cy,        olz = pz-cz;
    float oux = px-(cx+1.f),  ouy = py-(cy+1.f),  ouz = pz-(cz+1.f);
    f[0]=ocx; f[1]=ocy; f[2]=ocz;
    f[3]=olx; f[4]=oly; f[5]=olz;
    f[6]=oux; f[7]=ouy; f[8]=ouz;
    f[9]  = sqrtf(ocx*ocx+ocy*ocy+ocz*ocz);
    f[10] = sqrtf(olx*olx+oly*oly+olz*olz);
    f[11] = sqrtf(oux*oux+ouy*ouy+ouz*ouz);
    cellpad = ((int)cx+2)*(PD*ROWS) + ((int)cy+2)*ROWS + ((int)cz+2);
}

__global__ void __launch_bounds__(256,2)
point_kernel(const float* __restrict__ P0, const float* __restrict__ P1,
             const float* __restrict__ P2,
             const float* __restrict__ W1, const float* __restrict__ B1,
             const float* __restrict__ W2, const float* __restrict__ B2,
             const float* __restrict__ W3, const float* __restrict__ B3)
{
    __shared__ __align__(16) ull pW1[192], pW2[256], pW3[64];
    __shared__ ull pb1[16], pb2[16], pb3[4];
    int t = threadIdx.x;
    for (int i=t;i<192;i+=256) pW1[i]=pack2(W1[i],W1[i]);
    for (int i=t;i<256;i+=256) pW2[i]=pack2(W2[i],W2[i]);
    for (int i=t;i<64; i+=256) pW3[i]=pack2(W3[i],W3[i]);
    if (t<16){ pb1[t]=pack2(B1[t],B1[t]); pb2[t]=pack2(B2[t],B2[t]); }
    if (t<4)  pb3[t]=pack2(B3[t],B3[t]);
    __syncthreads();

    const float* pts = (blockIdx.y==0) ? P0 : (blockIdx.y==1 ? P1 : P2);
    int chan = blockIdx.y*4;

    long tid = (long)blockIdx.x*256 + t;
    long p0  = tid*2;
    if (p0 >= PPC) return;

    const float2* v = (const float2*)(pts + p0*3);
    float2 f0=v[0], f1=v[1], f2=v[2];
    float fa[12], fb[12]; int ca, cb;
    disty_one(f0.x, f0.y, f1.x, fa, ca);
    disty_one(f1.y, f2.x, f2.y, fb, cb);

    ull X[12];
    #pragma unroll
    for (int k=0;k<12;k++) X[k]=pack2(fa[k],fb[k]);

    // layer 1: 12->16 + ELU
    ull H[16];
    #pragma unroll
    for (int j=0;j<16;j+=2){
        ull a0=pb1[j], a1=pb1[j+1];
        #pragma unroll
        for (int k=0;k<12;k++){
            ulonglong2 w = *(const ulonglong2*)&pW1[k*16+j];
            a0 = fma2(X[k], w.x, a0);
            a1 = fma2(X[k], w.y, a1);
        }
        H[j]   = elu2(a0);
        H[j+1] = elu2(a1);
    }

    // layer 2: 16->16 + ELU
    ull H2[16];
    #pragma unroll
    for (int j=0;j<16;j+=2){
        ull a0=pb2[j], a1=pb2[j+1];
        #pragma unroll
        for (int k=0;k<16;k++){
            ulonglong2 w = *(const ulonglong2*)&pW2[k*16+j];
            a0 = fma2(H[k], w.x, a0);
            a1 = fma2(H[k], w.y, a1);
        }
        H2[j]   = elu2(a0);
        H2[j+1] = elu2(a1);
    }

    // layer 3: 16->4 + scatter-max (grid floor is 0; positives order as ints)
    int b = (int)(p0 / NPTS);
    int baseA = b*BSTR + chan*CSTR + ca;
    int baseB = b*BSTR + chan*CSTR + cb;
    #pragma unroll
    for (int j=0;j<4;j++){
        ull a = pb3[j];
        #pragma unroll
        for (int k=0;k<16;k++) a = fma2(H2[k], pW3[k*4+j], a);
        float v0, v1; unpack2(a, v0, v1);
        if (v0 > 0.f) atomicMax((int*)&g_grid[baseA + j*CSTR], __float_as_int(v0));
        if (v1 > 0.f) atomicMax((int*)&g_grid[baseB + j*CSTR], __float_as_int(v1));
    }
}

// ---------------- conv1: 12->8, k5, s2, p2 ; grid (oc,b)=32 blocks ----------
// writes raw conv output (no bias: cancels in BN) + per-block stats slot
__global__ void conv1_kernel(const float* __restrict__ w)
{
    __shared__ float s[CSTR];      // one padded input channel [19][19][21]
    __shared__ float wsm[200];     // [kd][kh][8] (kw padded)
    __shared__ float sRed[128];
    int oc = blockIdx.x, b = blockIdx.y, t = threadIdx.x;
    int owt = t & 1, oh = (t>>1)&7, od = t>>4;   // 128 threads

    float acc[4] = {0.f,0.f,0.f,0.f};

    for (int ic=0; ic<12; ic++){
        __syncthreads();
        const float4* g4 = (const float4*)(g_grid + (b*12+ic)*CSTR);
        for (int i=t; i<CSTR/4; i+=128) ((float4*)s)[i] = g4[i];
        if (t < 125){
            int kd=t/25, kh=(t%25)/5, kw=t%5;
            wsm[(kd*5+kh)*8+kw] = w[(oc*12+ic)*125 + t];
        }
        __syncthreads();

        #pragma unroll
        for (int kd=0;kd<5;kd++){
            int ip = 2*od + kd;
            #pragma unroll
            for (int kh=0;kh<5;kh++){
                int ih = 2*oh + kh;
                int base = ip*(PD*ROWS) + ih*ROWS + owt*8;
                float c[11];
                #pragma unroll
                for (int u=0;u<11;u++) c[u] = s[base+u];
                const float* wp = &wsm[(kd*5+kh)*8];
                #pragma unroll
                for (int o=0;o<4;o++){
                    #pragma unroll
                    for (int kw=0;kw<5;kw++)
                        acc[o] += c[2*o+kw] * wp[kw];
                }
            }
        }
    }

    int obase = b*4096 + oc*512 + od*64 + oh*8 + owt*4;
    float ls=0.f, lq=0.f;
    #pragma unroll
    for (int o=0;o<4;o++){ g_bufA[obase+o] = acc[o]; ls += acc[o]; lq += acc[o]*acc[o]; }

    sRed[t]=ls; __syncthreads();
    for (int o=64;o>0;o>>=1){ if (t<o) sRed[t]+=sRed[t+o]; __syncthreads(); }
    float tot = sRed[0]; __syncthreads();
    sRed[t]=lq; __syncthreads();
    for (int o=64;o>0;o>>=1){ if (t<o) sRed[t]+=sRed[t+o]; __syncthreads(); }
    if (t==0) g_slots0[oc*4+b] = make_float2(tot, sRed[0]);
}

// ---------------- convs 2..7: fused (input BN+ELU) + conv + stats -----------
// dir=0: bufA->bufB, slots0->slots1 ; dir=1: bufB->bufA, slots1->slots0
#define CONVS_SMEM ((13824+1600+8+8+128)*4)
__global__ void convs_kernel(int dir, const float* __restrict__ w,
                             const float* __restrict__ gin, const float* __restrict__ bin)
{
    extern __shared__ float dyn[];
    float* sIn  = dyn;             // [8][12][12][12]  (ic, h, w, d)
    float* wsm  = dyn + 13824;     // [ic][(kh*5+kw)*8 + kd]
    float* sSc  = wsm + 1600;
    float* sSh  = sSc + 8;
    float* sRed = sSh + 8;

    const float*  rin  = dir ? g_bufB   : g_bufA;
    float*        rout = dir ? g_bufA   : g_bufB;
    const float2* sin_ = dir ? g_slots1 : g_slots0;
    float2*       sout = dir ? g_slots0 : g_slots1;

    int oc = blockIdx.x, b = blockIdx.y, t = threadIdx.x;   // 128 threads

    if (t < 8){
        float sx=0.f, sy=0.f;
        #pragma unroll
        for (int q=0;q<4;q++){ float2 p = sin_[t*4+q]; sx+=p.x; sy+=p.y; }
        float m  = sx*(1.f/2048.f);
        float vr = sy*(1.f/2048.f) - m*m;
        float sc = gin[t]*rsqrtf(vr + 1e-5f);
        sSc[t]=sc; sSh[t]=bin[t]-m*sc;
    }
    float4 z4 = make_float4(0.f,0.f,0.f,0.f);
    for (int i=t;i<3456;i+=128) ((float4*)sIn)[i] = z4;
    for (int i=t;i<1000;i+=128){
        int ic=i/125, r=i%125, kd=r/25, kh=(r%25)/5, kw=r%5;
        wsm[ic*200 + (kh*5+kw)*8 + kd] = w[oc*1000 + i];   // FIX: oc offset
    }
    __syncthreads();

    const float4* r4 = (const float4*)(rin + b*4096);
    for (int i=t;i<1024;i+=128){
        float4 v = r4[i];
        int e = i*4;
        int ic = e>>9, d = (e>>6)&7, h = (e>>3)&7, w0 = e&7;
        float sc = sSc[ic], sh = sSh[ic];
        int bb = ic*1728 + (h+2)*144 + (d+2);
        sIn[bb + (w0+2)*12] = eluf(v.x*sc+sh);
        sIn[bb + (w0+3)*12] = eluf(v.y*sc+sh);
        sIn[bb + (w0+4)*12] = eluf(v.z*sc+sh);
        sIn[bb + (w0+5)*12] = eluf(v.w*sc+sh);
    }
    __syncthreads();

    int hw = t&63, oh = hw>>3, ow = hw&7, odt = t>>6;
    float acc[4] = {0.f,0.f,0.f,0.f};

    #pragma unroll
    for (int ic=0;ic<8;ic++){
        #pragma unroll
        for (int kh=0;kh<5;kh++){
            #pragma unroll
            for (int kw=0;kw<5;kw++){
                int ba = ic*1728 + (oh+kh)*144 + (ow+kw)*12 + odt*4;
                float4 c0 = *(const float4*)&sIn[ba];
                float4 c1 = *(const float4*)&sIn[ba+4];
                float col[8] = {c0.x,c0.y,c0.z,c0.w,c1.x,c1.y,c1.z,c1.w};
                const float* wp = &wsm[ic*200 + (kh*5+kw)*8];
                float4 wv = *(const float4*)wp;
                float wk[5] = {wv.x,wv.y,wv.z,wv.w,wp[4]};
                #pragma unroll
                for (int o=0;o<4;o++){
                    #pragma unroll
                    for (int kd=0;kd<5;kd++)
                        acc[o] += col[o+kd]*wk[kd];
                }
            }
        }
    }

    int obase = b*4096 + oc*512 + (odt*4)*64 + oh*8 + ow;
    float ls=0.f, lq=0.f;
    #pragma unroll
    for (int o=0;o<4;o++){ rout[obase + o*64] = acc[o]; ls+=acc[o]; lq+=acc[o]*acc[o]; }

    sRed[t]=ls; __syncthreads();
    for (int o=64;o>0;o>>=1){ if (t<o) sRed[t]+=sRed[t+o]; __syncthreads(); }
    float tot = sRed[0]; __syncthreads();
    sRed[t]=lq; __syncthreads();
    for (int o=64;o>0;o>>=1){ if (t<o) sRed[t]+=sRed[t+o]; __syncthreads(); }
    if (t==0) sout[oc*4+b] = make_float2(tot, sRed[0]);
}

// ---------------- final BN+ELU on layer-7 raw output ------------------------
__global__ void finalbn_kernel(float* __restrict__ out,
                               const float* __restrict__ gin, const float* __restrict__ bin)
{
    int c = blockIdx.x, t = threadIdx.x;   // 8 blocks x 256
    float sx=0.f, sy=0.f;
    #pragma unroll
    for (int q=0;q<4;q++){ float2 p = g_slots0[c*4+q]; sx+=p.x; sy+=p.y; }
    float m  = sx*(1.f/2048.f);
    float vr = sy*(1.f/2048.f) - m*m;
    float sc = gin[c]*rsqrtf(vr + 1e-5f);
    float sh = bin[c]-m*sc;
    #pragma unroll
    for (int r=0;r<8;r++){
        int e = t + r*256;
        int b = e>>9, sp = e&511;
        float v = g_bufA[b*4096 + c*512 + sp];
        out[(b*8+c)*512 + sp] = eluf(v*sc+sh);
    }
}

// ---------------------------------------------------------------------------
extern "C" void kernel_launch(void* const* d_in, const int* in_sizes, int n_in,
                              void* d_out, int out_size)
{
    const float* goals       = (const float*)d_in[0];
    const float* inputs      = (const float*)d_in[1];
    const float* backgrounds = (const float*)d_in[2];
    const float* W1 = (const float*)d_in[3];
    const float* b1 = (const float*)d_in[4];
    const float* W2 = (const float*)d_in[5];
    const float* b2 = (const float*)d_in[6];
    const float* W3 = (const float*)d_in[7];
    const float* b3 = (const float*)d_in[8];
    const float* conv1_w = (const float*)d_in[9];
    const float* bn1_g   = (const float*)d_in[11];
    const float* bn1_b   = (const float*)d_in[12];
    const float* convs_w = (const float*)d_in[13];
    const float* bns_g   = (const float*)d_in[15];
    const float* bns_b   = (const float*)d_in[16];
    float* out = (float*)d_out;

    cudaFuncSetAttribute(convs_kernel, cudaFuncAttributeMaxDynamicSharedMemorySize, CONVS_SMEM);

    zero_grid_kernel<<<GRIDN/256, 256>>>();

    dim3 pg((PPC/2 + 255)/256, 3);
    point_kernel<<<pg,256>>>(inputs, goals, backgrounds, W1,b1,W2,b2,W3,b3);

    dim3 cg(8,4);
    conv1_kernel<<<cg,128>>>(conv1_w);

    convs_kernel<<<cg,128,CONVS_SMEM>>>(0, convs_w,         bn1_g,    bn1_b);
    convs_kernel<<<cg,128,CONVS_SMEM>>>(1, convs_w +  8000, bns_g,    bns_b);
    convs_kernel<<<cg,128,CONVS_SMEM>>>(0, convs_w + 16000, bns_g+8,  bns_b+8);
    convs_kernel<<<cg,128,CONVS_SMEM>>>(1, convs_w + 24000, bns_g+16, bns_b+16);
    convs_kernel<<<cg,128,CONVS_SMEM>>>(0, convs_w + 32000, bns_g+24, bns_b+24);
    convs_kernel<<<cg,128,CONVS_SMEM>>>(1, convs_w + 40000, bns_g+32, bns_b+32);

    finalbn_kernel<<<8,256>>>(out, bns_g+40, bns_b+40);
}